// round 16
// baseline (speedup 1.0000x reference)
#include <cuda_runtime.h>
#include <cuda_bf16.h>
#include <math.h>
#include <stdint.h>

#define BQ   4096
#define NEX  16384
#define DIN  1024
#define DF   256
#define NLAB 28
#define DC   64
#define PV_SPLITS 8
#define KSPLIT (NEX/PV_SPLITS)   // 2048
#define TILES (KSPLIT/128)       // 16 key-tiles of 128 per CTA

// ---------------- scratch (device globals: allocation-free rule) ----------
__device__ __nv_bfloat16  g_FhB[(size_t)BQ*DIN];      // features bf16
__device__ __nv_bfloat16  g_Xh[(size_t)NEX*DIN];      // ex_features bf16
__device__ __nv_bfloat16  g_Wh[(size_t)DF*DIN];       // g_w bf16
__device__ __nv_bfloat16  g_Qh[(size_t)BQ*DF];        // l2-normed queries (bf16)
__device__ __nv_bfloat16  g_Kh[(size_t)NEX*DF];       // l2-normed exemplars (bf16)
__device__ __nv_bfloat16  g_Vt[(size_t)DC*NEX];       // V transposed (bf16)
__device__ float          g_num8[(size_t)PV_SPLITS*BQ*DC];
__device__ float          g_den[BQ];

// ---------------- helpers ---------------------------------------------------
__device__ __forceinline__ void mma_bf16(float c[4], const uint32_t a[4], const uint32_t b[2]){
    asm volatile(
        "mma.sync.aligned.m16n8k16.row.col.f32.bf16.bf16.f32 "
        "{%0,%1,%2,%3}, {%4,%5,%6,%7}, {%8,%9}, {%0,%1,%2,%3};\n"
        : "+f"(c[0]), "+f"(c[1]), "+f"(c[2]), "+f"(c[3])
        : "r"(a[0]), "r"(a[1]), "r"(a[2]), "r"(a[3]), "r"(b[0]), "r"(b[1]));
}
__device__ __forceinline__ void ldsm4(uint32_t& r0, uint32_t& r1, uint32_t& r2, uint32_t& r3,
                                      uint32_t addr){
    asm volatile("ldmatrix.sync.aligned.m8n8.x4.shared.b16 {%0,%1,%2,%3}, [%4];"
        : "=r"(r0), "=r"(r1), "=r"(r2), "=r"(r3) : "r"(addr));
}
__device__ __forceinline__ uint32_t pack_bf16(float x, float y){
    __nv_bfloat162 h = __floats2bfloat162_rn(x, y);
    return *(uint32_t*)&h;
}
__device__ __forceinline__ uint32_t smem_u32(const void* p){
    uint32_t a;
    asm("{ .reg .u64 t; cvta.to.shared.u64 t, %1; cvt.u32.u64 %0, t; }" : "=r"(a) : "l"(p));
    return a;
}
__device__ __forceinline__ void cp16(uint32_t dst, const void* src){
    asm volatile("cp.async.cg.shared.global [%0], [%1], 16;" :: "r"(dst), "l"(src));
}
#define CP_COMMIT() asm volatile("cp.async.commit_group;" ::: "memory")
#define CP_WAIT1()  asm volatile("cp.async.wait_group 1;" ::: "memory")
#define CP_WAIT2()  asm volatile("cp.async.wait_group 2;" ::: "memory")
#define CP_WAIT4()  asm volatile("cp.async.wait_group 4;" ::: "memory")

// ---------------- attn smem geometry (dynamic, occ-2) -----------------------
// Q: 64 rows x 256 feat (pad to 264)      = 33792 B
// K: 2 bufs x (128 keys x 64 feat pad 72) = 36864 B
// V: 2 bufs x (64 dc x 128 keys pad 136)  = 34816 B
#define QSTR 264
#define QOFF 0
#define QSZ  (64*QSTR*2)             // 33792
#define KOFF QSZ
#define KSTR 72
#define KBUF (128*KSTR*2)            // 18432
#define VOFF (KOFF + 2*KBUF)         // 70656
#define VSTR 136
#define VBUF (64*VSTR*2)             // 17408
#define SMEM_ATTN (VOFF + 2*VBUF)    // 105472

// ---------------- proj smem geometry (dynamic, occ-2) -----------------------
#define PASTR 40
#define PABUF (64*PASTR)
#define PBSTR 40
#define PBBUF (256*PBSTR)
#define PROJ_BOFF (2*PABUF*2)        // 10240 bytes
#define SMEM_PROJ (PROJ_BOFF + 2*PBBUF*2)   // 51200 bytes

// ---------------------------------------------------------------------------
__global__ void zero_kernel(float* out0){
    int i = blockIdx.x*blockDim.x + threadIdx.x;
    if (i < BQ) g_den[i] = 0.f;
    if (i == 0) out0[0] = 0.f;
}

// ---------------------------------------------------------------------------
__global__ void conv_kernel(const float* __restrict__ src,
                            __nv_bfloat16* __restrict__ dst, int n8){
    int i = blockIdx.x*blockDim.x + threadIdx.x;
    if (i >= n8) return;
    const float4* s = (const float4*)src + (size_t)i*2;
    float4 a = s[0], b = s[1];
    uint4 o = { pack_bf16(a.x,a.y), pack_bf16(a.z,a.w),
                pack_bf16(b.x,b.y), pack_bf16(b.z,b.w) };
    *((uint4*)dst + i) = o;
}

// ---------------------------------------------------------------------------
// projection + fused L2 normalize (unchanged from R14; occ 2)
__global__ __launch_bounds__(256, 2) void proj_kernel(){
    extern __shared__ char smem[];
    const uint32_t sb = smem_u32(smem);
    const int tid = threadIdx.x, lid = tid & 31, wid = tid >> 5;
    const int wm = wid & 1, wn = wid >> 1;
    const int g = lid >> 2, tig = lid & 3;
    const int m0 = blockIdx.x * 64;

    const __nv_bfloat16* Asrc;
    __nv_bfloat16* outp;
    if (m0 < BQ){ Asrc = g_FhB + (size_t)m0*DIN;        outp = g_Qh + (size_t)m0*DF; }
    else        { Asrc = g_Xh + (size_t)(m0-BQ)*DIN;    outp = g_Kh + (size_t)(m0-BQ)*DF; }

    auto loadC = [&](int kc, int buf){
        {
            int row = tid >> 2, seg = tid & 3;
            cp16(sb + buf*(PABUF*2) + (row*PASTR + seg*8)*2,
                 Asrc + (size_t)row*DIN + kc*32 + seg*8);
        }
        #pragma unroll
        for (int i = 0; i < 4; i++){
            int idx = tid + i*256, row = idx >> 2, seg = idx & 3;
            cp16(sb + PROJ_BOFF + buf*(PBBUF*2) + (row*PBSTR + seg*8)*2,
                 g_Wh + (size_t)row*DIN + kc*32 + seg*8);
        }
    };
    loadC(0, 0); CP_COMMIT();
    loadC(1, 1); CP_COMMIT();

    const int arow_l = lid & 15;
    const int acol_l = (lid >> 4) * 8;
    const int brow_l = ((lid >> 4) << 3) + (lid & 7);
    const int badd_l = ((lid >> 3) & 1) * 8;

    float acc[2][8][4] = {};

    for (int kc = 0; kc < 32; kc++){
        CP_WAIT1();
        __syncthreads();
        const uint32_t Ab = sb + (kc & 1)*(PABUF*2);
        const uint32_t Bb = sb + PROJ_BOFF + (kc & 1)*(PBBUF*2);
        #pragma unroll
        for (int ks = 0; ks < 2; ks++){
            uint32_t afr[2][4];
            #pragma unroll
            for (int mf = 0; mf < 2; mf++)
                ldsm4(afr[mf][0], afr[mf][1], afr[mf][2], afr[mf][3],
                      Ab + ((wm*32 + mf*16 + arow_l)*PASTR + ks*16 + acol_l)*2);
            uint32_t bfr[8][2];
            #pragma unroll
            for (int nb = 0; nb < 4; nb++)
                ldsm4(bfr[2*nb][0], bfr[2*nb][1], bfr[2*nb+1][0], bfr[2*nb+1][1],
                      Bb + ((wn*64 + nb*16 + brow_l)*PBSTR + ks*16 + badd_l)*2);
            #pragma unroll
            for (int mf = 0; mf < 2; mf++)
                #pragma unroll
                for (int nf = 0; nf < 8; nf++)
                    mma_bf16(acc[mf][nf], afr[mf], bfr[nf]);
        }
        __syncthreads();
        if (kc + 2 < 32) loadC(kc + 2, kc & 1);
        CP_COMMIT();
    }

    float* srow = (float*)smem;
    __syncthreads();
    if (tid < 64) srow[tid] = 0.f;
    __syncthreads();
    #pragma unroll
    for (int mf = 0; mf < 2; mf++){
        float ss0 = 0.f, ss1 = 0.f;
        #pragma unroll
        for (int nf = 0; nf < 8; nf++){
            ss0 += acc[mf][nf][0]*acc[mf][nf][0] + acc[mf][nf][1]*acc[mf][nf][1];
            ss1 += acc[mf][nf][2]*acc[mf][nf][2] + acc[mf][nf][3]*acc[mf][nf][3];
        }
        ss0 += __shfl_xor_sync(0xffffffffu, ss0, 1);
        ss0 += __shfl_xor_sync(0xffffffffu, ss0, 2);
        ss1 += __shfl_xor_sync(0xffffffffu, ss1, 1);
        ss1 += __shfl_xor_sync(0xffffffffu, ss1, 2);
        if (tig == 0){
            atomicAdd(&srow[wm*32 + mf*16 + g], ss0);
            atomicAdd(&srow[wm*32 + mf*16 + g + 8], ss1);
        }
    }
    __syncthreads();
    #pragma unroll
    for (int mf = 0; mf < 2; mf++){
        const int row = wm*32 + mf*16 + g;
        float i0 = 1.f / fmaxf(sqrtf(srow[row]),     1e-12f);
        float i1 = 1.f / fmaxf(sqrtf(srow[row + 8]), 1e-12f);
        #pragma unroll
        for (int nf = 0; nf < 8; nf++){
            const int col = wn*64 + nf*8 + 2*tig;
            *(uint32_t*)(outp + (size_t)row*DF + col) =
                pack_bf16(acc[mf][nf][0]*i0, acc[mf][nf][1]*i0);
            *(uint32_t*)(outp + (size_t)(row+8)*DF + col) =
                pack_bf16(acc[mf][nf][2]*i1, acc[mf][nf][3]*i1);
        }
    }
}

// ---------------------------------------------------------------------------
__global__ __launch_bounds__(256) void exrep_kernel(const float* __restrict__ exc,
                                                    const float* __restrict__ creps){
    __shared__ float cs[NLAB*DC];
    __shared__ float ex_s[64*NLAB];
    __shared__ float inv_s[64];
    const int r0 = blockIdx.x*64, tid = threadIdx.x;
    for (int i = tid; i < NLAB*DC; i += 256) cs[i] = creps[i];
    for (int i = tid; i < 64*NLAB; i += 256) ex_s[i] = exc[(size_t)r0*NLAB + i];
    __syncthreads();
    if (tid < 64){
        float s = 0.f;
        #pragma unroll
        for (int k = 0; k < NLAB; k++) s += fabsf(ex_s[tid*NLAB + k]);
        inv_s[tid] = 1.f / fmaxf(s, 1e-12f);
    }
    __syncthreads();
    const int d = tid & 63, rb = tid >> 6;
    uint32_t ov[8];
    #pragma unroll
    for (int rr = 0; rr < 16; rr += 2){
        const int ra = rb*16 + rr;
        float a0 = 0.f, a1 = 0.f;
        #pragma unroll
        for (int k = 0; k < NLAB; k++){
            float c = cs[k*DC + d];
            a0 += ex_s[ra*NLAB + k] * c;
            a1 += ex_s[(ra+1)*NLAB + k] * c;
        }
        ov[rr >> 1] = pack_bf16(a0*inv_s[ra], a1*inv_s[ra+1]);
    }
    __nv_bfloat16* dst = g_Vt + (size_t)d*NEX + r0 + rb*16;
    *(uint4*)dst       = make_uint4(ov[0], ov[1], ov[2], ov[3]);
    *((uint4*)dst + 1) = make_uint4(ov[4], ov[5], ov[6], ov[7]);
}

// ---------------------------------------------------------------------------
// Fused attention, occupancy 2. q-block 64, key-split 2048.
// Warps 4(M: 16 rows) x 2(N: 64 keys). K streamed as 128key x 64feat chunks
// (4 per key-tile), V double-buffered per key-tile.
// Commit order per tile: [K0 K1 K2 K3 V]; waits: 2,2,1,1 (S) and 4 (PV).
__global__ __launch_bounds__(256, 2) void attn_kernel(){
    extern __shared__ char smem[];
    const uint32_t sb = smem_u32(smem);
    const int tid = threadIdx.x, lid = tid & 31, wid = tid >> 5;
    const int wm = wid & 3, wn = wid >> 2;          // 4 M-warps x 2 N-warps
    const int g = lid >> 2, tig = lid & 3;
    const int q0 = blockIdx.x * 64;
    const int split = blockIdx.y;
    const int k0 = split * KSPLIT;

    // K chunk: 128 keys x 64 features (chunk c of tile t) = 1024 x 16B
    auto load_K = [&](int tile, int c, int buf){
        const size_t nb = (size_t)(k0 + tile*128);
        #pragma unroll
        for (int i = 0; i < 4; i++){
            int idx = tid + i*256, row = idx >> 3, seg = idx & 7;
            cp16(sb + KOFF + buf*KBUF + (row*KSTR + seg*8)*2,
                 g_Kh + (nb + row)*DF + c*64 + seg*8);
        }
    };
    auto load_V = [&](int tile){
        const int buf = tile & 1;
        #pragma unroll
        for (int i = 0; i < 4; i++){
            int idx = tid + i*256, row = idx >> 4, seg = idx & 15;
            cp16(sb + VOFF + buf*VBUF + (row*VSTR + seg*8)*2,
                 g_Vt + (size_t)row*NEX + k0 + tile*128 + seg*8);
        }
    };

    // prologue: G0 = {Q, K(0,0)}, G1 = {K(0,1)}, G2 = {V(0)}
    #pragma unroll
    for (int i = 0; i < 8; i++){
        int idx = tid + i*256, row = idx >> 5, seg = idx & 31;
        cp16(sb + QOFF + (row*QSTR + seg*8)*2,
             g_Qh + (size_t)(q0 + row)*DF + seg*8);
    }
    load_K(0, 0, 0); CP_COMMIT();
    load_K(0, 1, 1); CP_COMMIT();
    load_V(0);       CP_COMMIT();

    // ldmatrix lane geometry
    const int arow_l = lid & 15;
    const int acol_l = (lid >> 4) * 8;
    const int brow_l = ((lid >> 4) << 3) + (lid & 7);
    const int badd_l = ((lid >> 3) & 1) * 8;

    float num[8][4] = {};       // 16 q-rows x 64 dc per warp
    float den[2] = {};
    float sacc[8][4];           // 16 q-rows x 64 keys per warp

    for (int t = 0; t < TILES; t++){
        #pragma unroll
        for (int nf = 0; nf < 8; nf++)
            #pragma unroll
            for (int x = 0; x < 4; x++) sacc[nf][x] = 0.f;

        // ---- S phase: 4 feature-chunks of 64 ----
        #pragma unroll
        for (int c = 0; c < 4; c++){
            if (c < 2) { CP_WAIT2(); } else { CP_WAIT1(); }
            __syncthreads();
            const uint32_t Kb = sb + KOFF + (c & 1)*KBUF;
            #pragma unroll
            for (int ks = 0; ks < 4; ks++){
                uint32_t afr[4];
                ldsm4(afr[0], afr[1], afr[2], afr[3],
                      sb + QOFF + ((wm*16 + arow_l)*QSTR + c*64 + ks*16 + acol_l)*2);
                uint32_t bfr[8][2];
                #pragma unroll
                for (int nb = 0; nb < 4; nb++)
                    ldsm4(bfr[2*nb][0], bfr[2*nb][1], bfr[2*nb+1][0], bfr[2*nb+1][1],
                          Kb + ((wn*64 + nb*16 + brow_l)*KSTR + ks*16 + badd_l)*2);
                #pragma unroll
                for (int nf = 0; nf < 8; nf++)
                    mma_bf16(sacc[nf], afr, bfr[nf]);
            }
            __syncthreads();                       // readers done with buf c&1
            // prefetch chunk (stream index 4t + c + 2)
            const int j = 4*t + c + 2;
            if (j < 4*TILES) load_K((j >> 2), j & 3, j & 1);
            CP_COMMIT();                           // uniform (empty at tail)
        }

        // ---- transform: a = s^3, den (registers) ----
        #pragma unroll
        for (int nf = 0; nf < 8; nf++){
            float a0 = sacc[nf][0]; a0 = a0*a0*a0;
            float a1 = sacc[nf][1]; a1 = a1*a1*a1;
            float a2 = sacc[nf][2]; a2 = a2*a2*a2;
            float a3 = sacc[nf][3]; a3 = a3*a3*a3;
            den[0] += fabsf(a0) + fabsf(a1);
            den[1] += fabsf(a2) + fabsf(a3);
            sacc[nf][0] = a0; sacc[nf][1] = a1;
            sacc[nf][2] = a2; sacc[nf][3] = a3;
        }

        // ---- PV: A from sacc registers, B = V fragments ----
        CP_WAIT4();                                // V(t) complete
        __syncthreads();
        const uint32_t Vb = sb + VOFF + (t & 1)*VBUF;
        #pragma unroll
        for (int kst = 0; kst < 4; kst++){
            uint32_t av[4];
            av[0] = pack_bf16(sacc[2*kst][0],   sacc[2*kst][1]);
            av[1] = pack_bf16(sacc[2*kst][2],   sacc[2*kst][3]);
            av[2] = pack_bf16(sacc[2*kst+1][0], sacc[2*kst+1][1]);
            av[3] = pack_bf16(sacc[2*kst+1][2], sacc[2*kst+1][3]);
            uint32_t bv[8][2];
            #pragma unroll
            for (int db = 0; db < 4; db++)
                ldsm4(bv[2*db][0], bv[2*db][1], bv[2*db+1][0], bv[2*db+1][1],
                      Vb + ((db*16 + brow_l)*VSTR + wn*64 + kst*16 + badd_l)*2);
            #pragma unroll
            for (int dt = 0; dt < 8; dt++)
                mma_bf16(num[dt], av, bv[dt]);
        }
        // V(t+1) into buf (t+1)&1 — last read by PV(t-1), long done
        if (t + 1 < TILES) load_V(t + 1);
        CP_COMMIT();                               // uniform (empty at tail)
    }

    // ---- final reductions ----
    float* rbuf = (float*)smem;                    // 64 x 68 floats (17.4KB in Q region)
    float* sden = (float*)(smem + 64*68*4);
    __syncthreads();
    if (tid < 64) sden[tid] = 0.f;
    if (wn == 1){
        const int r = wm*16 + g;
        #pragma unroll
        for (int dt = 0; dt < 8; dt++){
            *(float2*)&rbuf[r*68 + dt*8 + 2*tig] =
                make_float2(num[dt][0], num[dt][1]);
            *(float2*)&rbuf[(r+8)*68 + dt*8 + 2*tig] =
                make_float2(num[dt][2], num[dt][3]);
        }
    }
    __syncthreads();
    {
        float d0 = den[0], d1 = den[1];
        d0 += __shfl_xor_sync(0xffffffffu, d0, 1);
        d0 += __shfl_xor_sync(0xffffffffu, d0, 2);
        d1 += __shfl_xor_sync(0xffffffffu, d1, 1);
        d1 += __shfl_xor_sync(0xffffffffu, d1, 2);
        if (tig == 0){
            atomicAdd(&sden[wm*16 + g], d0);
            atomicAdd(&sden[wm*16 + g + 8], d1);
        }
    }
    if (wn == 0){
        float* outb = g_num8 + (size_t)split*BQ*DC;
        const int r = wm*16 + g;
        #pragma unroll
        for (int dt = 0; dt < 8; dt++){
            float2 p0 = *(float2*)&rbuf[r*68 + dt*8 + 2*tig];
            float2 p1 = *(float2*)&rbuf[(r+8)*68 + dt*8 + 2*tig];
            *(float2*)(outb + (size_t)(q0 + r)*DC + dt*8 + 2*tig) =
                make_float2(num[dt][0] + p0.x, num[dt][1] + p0.y);
            *(float2*)(outb + (size_t)(q0 + r + 8)*DC + dt*8 + 2*tig) =
                make_float2(num[dt][2] + p1.x, num[dt][3] + p1.y);
        }
    }
    __syncthreads();
    if (tid < 64) atomicAdd(&g_den[q0 + tid], sden[tid]);
}

// ---------------------------------------------------------------------------
__global__ void loss_kernel(const float* __restrict__ labels,
                            const float* __restrict__ creps,
                            float* __restrict__ out){
    __shared__ float echo_s[DC];
    const int b = blockIdx.x, t = threadIdx.x;
    float inv = 1.f / fmaxf(g_den[b], 1e-12f);
    float n0 = 0.f, n1 = 0.f;
    #pragma unroll
    for (int s = 0; s < PV_SPLITS; s++){
        const float* p = g_num8 + ((size_t)s*BQ + b)*DC;
        n0 += p[t];
        n1 += p[t + 32];
    }
    echo_s[t]      = n0 * inv;
    echo_s[t + 32] = n1 * inv;
    __syncwarp();
    float le = 0.f;
    if (t < NLAB){
        float ss = 0.f;
        #pragma unroll
        for (int d = 0; d < DC; d++){
            float df = echo_s[d] - creps[t*DC + d];
            ss += df*df;
        }
        float x = -sqrtf(ss);
        out[1 + (size_t)b*NLAB + t] = x;
        float y = labels[(size_t)b*NLAB + t];
        le = log1pf(expf(x)) - y*x;
    }
    #pragma unroll
    for (int o = 16; o > 0; o >>= 1) le += __shfl_down_sync(0xffffffffu, le, o);
    if (t == 0) atomicAdd(out, le * (1.f/((float)BQ*(float)NLAB)));
}

// ---------------------------------------------------------------------------
extern "C" void kernel_launch(void* const* d_in, const int* in_sizes, int n_in,
                              void* d_out, int out_size){
    const float* features    = (const float*)d_in[0];
    const float* labels      = (const float*)d_in[1];
    const float* ex_features = (const float*)d_in[2];
    const float* ex_classes  = (const float*)d_in[3];
    const float* g_w         = (const float*)d_in[4];
    const float* class_reps  = (const float*)d_in[5];
    float* out = (float*)d_out;

    __nv_bfloat16 *pFh, *pXh, *pWh;
    cudaGetSymbolAddress((void**)&pFh, g_FhB);
    cudaGetSymbolAddress((void**)&pXh, g_Xh);
    cudaGetSymbolAddress((void**)&pWh, g_Wh);

    static int attr_done = 0;
    if (!attr_done){
        cudaFuncSetAttribute(proj_kernel, cudaFuncAttributeMaxDynamicSharedMemorySize, SMEM_PROJ);
        cudaFuncSetAttribute(attn_kernel, cudaFuncAttributeMaxDynamicSharedMemorySize, SMEM_ATTN);
        attr_done = 1;
    }

    zero_kernel<<<(BQ + 255)/256, 256>>>(out);

    conv_kernel<<<(BQ*DIN/8 + 255)/256, 256>>>(features, pFh, BQ*DIN/8);
    conv_kernel<<<(NEX*DIN/8 + 255)/256, 256>>>(ex_features, pXh, NEX*DIN/8);
    conv_kernel<<<(DF*DIN/8 + 255)/256, 256>>>(g_w, pWh, DF*DIN/8);

    proj_kernel<<<(BQ + NEX)/64, 256, SMEM_PROJ>>>();
    exrep_kernel<<<NEX/64, 256>>>(ex_classes, class_reps);
    attn_kernel<<<dim3(BQ/64, PV_SPLITS), 256, SMEM_ATTN>>>();
    loss_kernel<<<BQ, 32>>>(labels, class_reps, out);
}